// round 2
// baseline (speedup 1.0000x reference)
#include <cuda_runtime.h>
#include <cstdint>

// ---------------------------------------------------------------------------
// Fused LSTM cell: gates = x@Wx + h@Wh + b ; h_t = o*tanh(c_t), c_t = c*f+i*g
// B=4096, IN=H=2048. TF32 mma.sync GEMM, fused activation epilogue.
// Output: d_out[0 .. B*H)   = h_t
//         d_out[B*H .. 2BH) = c_t
// ---------------------------------------------------------------------------

#define BDIM 4096
#define HDIM 2048
#define BM 128
#define BN 64          // per gate; CTA really computes 128 x (64*4 gates)
#define BK 32
#define NTHREADS 256
#define A_STRIDE 36    // words, padded (conflict-free: bank = (4r+c)&31)
#define B_STRIDE 72    // words, padded (conflict-free: bank = (8k+n)&31)
#define A_TILE_WORDS (BM * A_STRIDE)                    // 4608
#define B_TILE_WORDS (BK * B_STRIDE)                    // 2304
#define STAGE_WORDS  (A_TILE_WORDS + 4 * B_TILE_WORDS)  // 13824 (55296 B)
#define SMEM_BYTES   (2 * STAGE_WORDS * 4)              // 110592 B
#define TOT_KSTEPS   128                                // 64 x-phase + 64 h-phase

__device__ __forceinline__ uint32_t smem_u32(const void* p) {
    return (uint32_t)__cvta_generic_to_shared(p);
}

__device__ __forceinline__ void cp16(uint32_t dst, const void* src) {
    asm volatile("cp.async.cg.shared.global [%0], [%1], 16;\n" :: "r"(dst), "l"(src));
}

__device__ __forceinline__ uint32_t f2tf32(float f) {
    uint32_t u;
    asm("cvt.rna.tf32.f32 %0, %1;" : "=r"(u) : "f"(f));
    return u;
}

__device__ __forceinline__ float sigmoidf_(float x) {
    return 1.0f / (1.0f + __expf(-x));
}

__global__ void __launch_bounds__(NTHREADS, 1)
lstm_fused_kernel(const float* __restrict__ x, const float* __restrict__ h,
                  const float* __restrict__ c,
                  const float* __restrict__ wxi, const float* __restrict__ wxf,
                  const float* __restrict__ wxo, const float* __restrict__ wxc,
                  const float* __restrict__ whi, const float* __restrict__ whf,
                  const float* __restrict__ who, const float* __restrict__ whc,
                  const float* __restrict__ bi, const float* __restrict__ bf,
                  const float* __restrict__ bo, const float* __restrict__ bc,
                  float* __restrict__ out)
{
    extern __shared__ float smem[];
    const int tid  = threadIdx.x;
    const int lane = tid & 31;
    const int warp = tid >> 5;
    const int warpM = warp & 1;   // 2 warps along M (64 rows each)
    const int warpN = warp >> 1;  // 4 warps along N (16 cols each)
    const int rowBase = blockIdx.x * BM;   // x fastest => col-tile L2 reuse
    const int colBase = blockIdx.y * BN;

    // accumulators: [gate][mma_m(4)][mma_n(2)][4]
    float acc[4][4][2][4];
    #pragma unroll
    for (int g = 0; g < 4; g++)
        #pragma unroll
        for (int m = 0; m < 4; m++)
            #pragma unroll
            for (int n = 0; n < 2; n++)
                #pragma unroll
                for (int r = 0; r < 4; r++) acc[g][m][n][r] = 0.0f;

    const float* Wx[4] = {wxi, wxf, wxo, wxc};
    const float* Wh[4] = {whi, whf, who, whc};

    auto load_stage = [&](int ks, int buf) {
        const int phase = ks >> 6;
        const int kbase = (ks & 63) * BK;
        const float* A = phase ? h : x;
        float* s = smem + buf * STAGE_WORDS;
        // A tile: 128 x 32 fp32, 1024 16B chunks
        #pragma unroll
        for (int i = 0; i < 4; i++) {
            int cid = i * 256 + tid;
            int r = cid >> 3, c4 = (cid & 7) * 4;
            cp16(smem_u32(s + r * A_STRIDE + c4),
                 A + (size_t)(rowBase + r) * HDIM + kbase + c4);
        }
        // 4 weight tiles: 32 x 64 fp32 each, 512 chunks each
        #pragma unroll
        for (int g = 0; g < 4; g++) {
            const float* W = phase ? Wh[g] : Wx[g];
            float* sB = s + A_TILE_WORDS + g * B_TILE_WORDS;
            #pragma unroll
            for (int j = 0; j < 2; j++) {
                int cid = j * 256 + tid;              // 0..511
                int k = cid >> 4, c4 = (cid & 15) * 4;
                cp16(smem_u32(sB + k * B_STRIDE + c4),
                     W + (size_t)(kbase + k) * HDIM + colBase + c4);
            }
        }
        asm volatile("cp.async.commit_group;\n");
    };

    load_stage(0, 0);

    for (int ks = 0; ks < TOT_KSTEPS; ks++) {
        if (ks + 1 < TOT_KSTEPS) {
            load_stage(ks + 1, (ks + 1) & 1);
            asm volatile("cp.async.wait_group 1;\n" ::: "memory");
        } else {
            asm volatile("cp.async.wait_group 0;\n" ::: "memory");
        }
        __syncthreads();

        const float* s  = smem + (ks & 1) * STAGE_WORDS;
        const float* sA = s;

        #pragma unroll
        for (int k8 = 0; k8 < 4; k8++) {
            // A fragments (shared across all 4 gates): m16n8k8 row-major
            uint32_t a[4][4];
            const int ar = warpM * 64 + (lane >> 2);
            const int ac = k8 * 8 + (lane & 3);
            #pragma unroll
            for (int m = 0; m < 4; m++) {
                const float* base = sA + (ar + m * 16) * A_STRIDE + ac;
                a[m][0] = f2tf32(base[0]);
                a[m][1] = f2tf32(base[8 * A_STRIDE]);
                a[m][2] = f2tf32(base[4]);
                a[m][3] = f2tf32(base[8 * A_STRIDE + 4]);
            }
            #pragma unroll
            for (int g = 0; g < 4; g++) {
                const float* sB = s + A_TILE_WORDS + g * B_TILE_WORDS;
                #pragma unroll
                for (int n = 0; n < 2; n++) {
                    const int bn = warpN * 16 + n * 8 + (lane >> 2);
                    const int bk = k8 * 8 + (lane & 3);
                    uint32_t b0 = f2tf32(sB[bk * B_STRIDE + bn]);
                    uint32_t b1 = f2tf32(sB[(bk + 4) * B_STRIDE + bn]);
                    #pragma unroll
                    for (int m = 0; m < 4; m++) {
                        float* ca = acc[g][m][n];
                        asm volatile(
                            "mma.sync.aligned.m16n8k8.row.col.f32.tf32.tf32.f32 "
                            "{%0,%1,%2,%3}, {%4,%5,%6,%7}, {%8,%9}, {%0,%1,%2,%3};\n"
                            : "+f"(ca[0]), "+f"(ca[1]), "+f"(ca[2]), "+f"(ca[3])
                            : "r"(a[m][0]), "r"(a[m][1]), "r"(a[m][2]), "r"(a[m][3]),
                              "r"(b0), "r"(b1));
                    }
                }
            }
        }
        __syncthreads();
    }

    // ---- fused epilogue: bias + activations + cell update ----
    const int r0 = rowBase + warpM * 64 + (lane >> 2);
    const int c0 = colBase + warpN * 16 + (lane & 3) * 2;
    const size_t BH = (size_t)BDIM * HDIM;

    #pragma unroll
    for (int m = 0; m < 4; m++) {
        #pragma unroll
        for (int n = 0; n < 2; n++) {
            #pragma unroll
            for (int rr = 0; rr < 2; rr++) {
                const int row = r0 + m * 16 + rr * 8;
                #pragma unroll
                for (int cc = 0; cc < 2; cc++) {
                    const int col = c0 + n * 8 + cc;
                    const int ai = rr * 2 + cc;
                    float gi = acc[0][m][n][ai] + bi[col];
                    float gf = acc[1][m][n][ai] + bf[col];
                    float go = acc[2][m][n][ai] + bo[col];
                    float gc = acc[3][m][n][ai] + bc[col];
                    float it = sigmoidf_(gi);
                    float ft = sigmoidf_(gf);
                    float ot = sigmoidf_(go);
                    float gt = tanhf(gc);
                    float cin = c[(size_t)row * HDIM + col];
                    float ct = cin * ft + it * gt;
                    float ht = ot * tanhf(ct);
                    out[(size_t)row * HDIM + col] = ht;
                    out[BH + (size_t)row * HDIM + col] = ct;
                }
            }
        }
    }
}

extern "C" void kernel_launch(void* const* d_in, const int* in_sizes, int n_in,
                              void* d_out, int out_size) {
    (void)in_sizes; (void)n_in; (void)out_size;
    const float* x   = (const float*)d_in[0];
    const float* h   = (const float*)d_in[1];
    const float* c   = (const float*)d_in[2];
    const float* wxi = (const float*)d_in[3];
    const float* wxf = (const float*)d_in[4];
    const float* wxo = (const float*)d_in[5];
    const float* wxc = (const float*)d_in[6];
    const float* whi = (const float*)d_in[7];
    const float* whf = (const float*)d_in[8];
    const float* who = (const float*)d_in[9];
    const float* whc = (const float*)d_in[10];
    const float* bi  = (const float*)d_in[11];
    const float* bf  = (const float*)d_in[12];
    const float* bo  = (const float*)d_in[13];
    const float* bc  = (const float*)d_in[14];
    float* out = (float*)d_out;

    cudaFuncSetAttribute(lstm_fused_kernel,
                         cudaFuncAttributeMaxDynamicSharedMemorySize, SMEM_BYTES);

    dim3 grid(BDIM / BM, HDIM / BN);   // (32, 32): x fastest -> weight reuse in L2
    lstm_fused_kernel<<<grid, NTHREADS, SMEM_BYTES>>>(
        x, h, c, wxi, wxf, wxo, wxc, whi, whf, who, whc, bi, bf, bo, bc, out);
}

// round 7
// speedup vs baseline: 2.4322x; 2.4322x over previous
#include <cuda_runtime.h>
#include <cuda_fp16.h>
#include <cstdint>

// ---------------------------------------------------------------------------
// LSTM cell, fp16 mma.sync (m16n8k16) GEMM + fused epilogue.
//  Pre-pass 1: WT[gate*2048+n][k] = half(W[k][n]),  k = [x-phase | h-phase]
//  Pre-pass 2: XH[b][k] = half([x|h][b][k])
//  Main: CTA = 128 rows x (4 gates x 64 cols), acc fp32 in regs,
//        ldmatrix fragment loads, 3-stage cp.async pipeline.
//  Out: [h_t ; c_t], fp32.
// ---------------------------------------------------------------------------

#define HD    2048
#define BB    4096
#define KTOT  4096
#define BM    128
#define BN    64            // cols per gate per CTA
#define BK    32            // halves per stage
#define NSTG  (KTOT/BK)     // 128
#define NBUF  3
#define AST   40            // A smem stride in halves (padded)
#define BST   40
#define A_HALVES (BM*AST)                 // 5120
#define B_HALVES (256*BST)                // 10240
#define STG_HALVES (A_HALVES + B_HALVES)  // 15360 (30720 B)
#define SMEM_BYTES (NBUF*STG_HALVES*2)    // 92160

__device__ __half d_WT[(size_t)4*2048*4096];   // 64 MB
__device__ __half d_XH[(size_t)4096*4096];     // 32 MB

__device__ __forceinline__ uint32_t su32(const void* p) {
    return (uint32_t)__cvta_generic_to_shared(p);
}
__device__ __forceinline__ void cp16(uint32_t d, const void* s) {
    asm volatile("cp.async.cg.shared.global [%0], [%1], 16;" :: "r"(d), "l"(s));
}
__device__ __forceinline__ void ldsm4(uint32_t* r, uint32_t a) {
    asm volatile("ldmatrix.sync.aligned.m8n8.x4.shared.b16 {%0,%1,%2,%3}, [%4];"
                 : "=r"(r[0]), "=r"(r[1]), "=r"(r[2]), "=r"(r[3]) : "r"(a));
}
__device__ __forceinline__ void mma16816(float* c, const uint32_t* a, const uint32_t* b) {
    asm volatile("mma.sync.aligned.m16n8k16.row.col.f32.f16.f16.f32 "
                 "{%0,%1,%2,%3}, {%4,%5,%6,%7}, {%8,%9}, {%0,%1,%2,%3};"
                 : "+f"(c[0]), "+f"(c[1]), "+f"(c[2]), "+f"(c[3])
                 : "r"(a[0]), "r"(a[1]), "r"(a[2]), "r"(a[3]), "r"(b[0]), "r"(b[1]));
}

// ---- pre-pass: transpose + convert weights: WT[g*2048+n][ph*2048+k] ----
__global__ void prep_w(const float* __restrict__ w0, const float* __restrict__ w1,
                       const float* __restrict__ w2, const float* __restrict__ w3,
                       const float* __restrict__ w4, const float* __restrict__ w5,
                       const float* __restrict__ w6, const float* __restrict__ w7) {
    __shared__ float t[32][33];
    const int z = blockIdx.z;                 // phase = z>>2, gate = z&3
    const float* W;
    switch (z) {
        case 0: W = w0; break; case 1: W = w1; break;
        case 2: W = w2; break; case 3: W = w3; break;
        case 4: W = w4; break; case 5: W = w5; break;
        case 6: W = w6; break; default: W = w7; break;
    }
    const int k0 = blockIdx.x * 32, n0 = blockIdx.y * 32;
    const int tx = threadIdx.x, ty = threadIdx.y;
    #pragma unroll
    for (int j = 0; j < 4; j++)
        t[ty + j * 8][tx] = W[(size_t)(k0 + ty + j * 8) * HD + n0 + tx];
    __syncthreads();
    const int gate = z & 3, phase = z >> 2;
    #pragma unroll
    for (int j = 0; j < 4; j++)
        d_WT[(size_t)(gate * 2048 + n0 + ty + j * 8) * KTOT + phase * 2048 + k0 + tx] =
            __float2half_rn(t[tx][ty + j * 8]);
}

// ---- pre-pass: pack + convert activations: XH[b] = [x | h] ----
__global__ void prep_a(const float* __restrict__ x, const float* __restrict__ h) {
    const int idx = blockIdx.x * 256 + threadIdx.x;    // one float4 -> 4 halves
    const int b = idx >> 10;
    const int k = (idx & 1023) * 4;
    const float* s = (k < HD) ? (x + (size_t)b * HD + k)
                              : (h + (size_t)b * HD + (k - HD));
    float4 v = *(const float4*)s;
    __half2 lo = __floats2half2_rn(v.x, v.y);
    __half2 hi = __floats2half2_rn(v.z, v.w);
    *(uint2*)(d_XH + (size_t)b * KTOT + k) =
        make_uint2(*(uint32_t*)&lo, *(uint32_t*)&hi);
}

// ---- main fused GEMM + LSTM epilogue ----
__global__ void __launch_bounds__(256, 1)
lstm_hmma(const float* __restrict__ cin,
          const float* __restrict__ bi, const float* __restrict__ bf,
          const float* __restrict__ bo, const float* __restrict__ bc,
          float* __restrict__ out) {
    extern __shared__ __half smem[];
    const int tid = threadIdx.x, lane = tid & 31, warp = tid >> 5;
    const int warpM = warp & 1;        // 2 warps along M (64 rows)
    const int warpN = warp >> 1;       // 4 warps along N (16 cols/gate)
    const int rowBase = blockIdx.x * BM;
    const int colBase = blockIdx.y * BN;

    float acc[4][4][2][4];
    #pragma unroll
    for (int g = 0; g < 4; g++)
        #pragma unroll
        for (int m = 0; m < 4; m++)
            #pragma unroll
            for (int n = 0; n < 2; n++)
                #pragma unroll
                for (int r = 0; r < 4; r++) acc[g][m][n][r] = 0.0f;

    // ldmatrix per-lane source offsets (halves), k16-invariant parts
    // A: matrix mi = lane>>3: {m0-7,k0-7},{m8-15,k0-7},{m0-7,k8-15},{m8-15,k8-15}
    const int mi = lane >> 3;
    const int aRow = warpM * 64 + (lane & 7) + (mi & 1) * 8;     // + mtile*16
    const int aKoff = (mi >> 1) * 8;                              // + k16*16
    // B: matrix mi: {n0-7,k0-7},{n0-7,k8-15},{n8-15,k0-7},{n8-15,k8-15}
    const int bRow = warpN * 16 + (lane & 7) + (mi >> 1) * 8;    // + g*64
    const int bKoff = (mi & 1) * 8;

    auto load_stage = [&](int s, int buf) {
        __half* st = smem + buf * STG_HALVES;
        const int kb = s * BK;
        // A: 128 rows x 32 halves = 512 x 16B
        #pragma unroll
        for (int i = 0; i < 2; i++) {
            const int ci = i * 256 + tid;
            const int r = ci >> 2, kc = ci & 3;
            cp16(su32(st + r * AST + kc * 8),
                 d_XH + (size_t)(rowBase + r) * KTOT + kb + kc * 8);
        }
        // B: 256 n-rows x 32 halves = 1024 x 16B
        __half* sb = st + A_HALVES;
        #pragma unroll
        for (int i = 0; i < 4; i++) {
            const int ci = i * 256 + tid;
            const int n = ci >> 2, kc = ci & 3;
            const int g = n >> 6, nc = colBase + (n & 63);
            cp16(su32(sb + n * BST + kc * 8),
                 d_WT + (size_t)(g * 2048 + nc) * KTOT + kb + kc * 8);
        }
        asm volatile("cp.async.commit_group;");
    };

    load_stage(0, 0);
    load_stage(1, 1);

    for (int s = 0; s < NSTG; s++) {
        if (s + 2 < NSTG) {
            load_stage(s + 2, (s + 2) % NBUF);
            asm volatile("cp.async.wait_group 2;" ::: "memory");
        } else {
            asm volatile("cp.async.wait_group 0;" ::: "memory");
        }
        __syncthreads();

        const __half* st = smem + (s % NBUF) * STG_HALVES;
        const uint32_t sA = su32(st);
        const uint32_t sB = su32(st + A_HALVES);

        #pragma unroll
        for (int k16 = 0; k16 < 2; k16++) {
            uint32_t a[4][4];
            #pragma unroll
            for (int m = 0; m < 4; m++)
                ldsm4(a[m], sA + ((aRow + m * 16) * AST + k16 * 16 + aKoff) * 2);
            #pragma unroll
            for (int g = 0; g < 4; g++) {
                uint32_t b[4];
                ldsm4(b, sB + ((g * 64 + bRow) * BST + k16 * 16 + bKoff) * 2);
                #pragma unroll
                for (int m = 0; m < 4; m++) {
                    mma16816(acc[g][m][0], a[m], b);
                    mma16816(acc[g][m][1], a[m], b + 2);
                }
            }
        }
        __syncthreads();
    }

    // ---- fused epilogue: bias + activations + cell update ----
    const int r0 = rowBase + warpM * 64 + (lane >> 2);
    const int c0 = colBase + warpN * 16 + (lane & 3) * 2;
    const size_t BH = (size_t)BB * HD;

    #pragma unroll
    for (int m = 0; m < 4; m++) {
        #pragma unroll
        for (int n = 0; n < 2; n++) {
            #pragma unroll
            for (int rr = 0; rr < 2; rr++) {
                const int row = r0 + m * 16 + rr * 8;
                #pragma unroll
                for (int cc = 0; cc < 2; cc++) {
                    const int col = c0 + n * 8 + cc;
                    const int ai = rr * 2 + cc;
                    float gi = acc[0][m][n][ai] + bi[col];
                    float gf = acc[1][m][n][ai] + bf[col];
                    float go = acc[2][m][n][ai] + bo[col];
                    float gc = acc[3][m][n][ai] + bc[col];
                    float it = 1.f / (1.f + __expf(-gi));
                    float ft = 1.f / (1.f + __expf(-gf));
                    float ot = 1.f / (1.f + __expf(-go));
                    float gt = 1.f - 2.f / (__expf(2.f * gc) + 1.f);
                    float cv = cin[(size_t)row * HD + col];
                    float ct = cv * ft + it * gt;
                    float ht = ot * (1.f - 2.f / (__expf(2.f * ct) + 1.f));
                    out[(size_t)row * HD + col] = ht;
                    out[BH + (size_t)row * HD + col] = ct;
                }
            }
        }
    }
}

extern "C" void kernel_launch(void* const* d_in, const int* in_sizes, int n_in,
                              void* d_out, int out_size) {
    (void)in_sizes; (void)n_in; (void)out_size;
    const float* x   = (const float*)d_in[0];
    const float* h   = (const float*)d_in[1];
    const float* c   = (const float*)d_in[2];
    const float* wxi = (const float*)d_in[3];
    const float* wxf = (const float*)d_in[4];
    const float* wxo = (const float*)d_in[5];
    const float* wxc = (const float*)d_in[6];
    const float* whi = (const float*)d_in[7];
    const float* whf = (const float*)d_in[8];
    const float* who = (const float*)d_in[9];
    const float* whc = (const float*)d_in[10];
    const float* bi  = (const float*)d_in[11];
    const float* bf  = (const float*)d_in[12];
    const float* bo  = (const float*)d_in[13];
    const float* bc  = (const float*)d_in[14];
    float* out = (float*)d_out;

    cudaFuncSetAttribute(lstm_hmma,
                         cudaFuncAttributeMaxDynamicSharedMemorySize, SMEM_BYTES);

    prep_a<<<(BB * KTOT / 4) / 256, 256>>>(x, h);
    prep_w<<<dim3(64, 64, 8), dim3(32, 8)>>>(wxi, wxf, wxo, wxc, whi, whf, who, whc);
    lstm_hmma<<<dim3(BB / BM, HD / BN), 256, SMEM_BYTES>>>(c, bi, bf, bo, bc, out);
}

// round 8
// speedup vs baseline: 2.8557x; 1.1741x over previous
#include <cuda_runtime.h>
#include <cuda_fp16.h>
#include <cstdint>

// ---------------------------------------------------------------------------
// LSTM cell, fp16 mma.sync (m16n8k16) GEMM + fused epilogue.
//  Pre-pass 1: WT[gate*2048+n][k] = half(W[k][n]),  k = [x-phase | h-phase]
//  Pre-pass 2: XH[b][k] = half([x|h][b][k])
//  Main: CTA = 128 rows x (4 gates x 64 cols), fp32 acc in regs,
//        ldmatrix fragment loads, BK=64, 4-buffer / 1-sync-per-stage pipeline.
//  Out: [h_t ; c_t], fp32.
// ---------------------------------------------------------------------------

#define HD    2048
#define BB    4096
#define KTOT  4096
#define BM    128
#define BN    64            // cols per gate per CTA
#define BK    64            // halves per stage
#define NSTG  (KTOT/BK)     // 64
#define NBUF  4
#define AST   72            // smem stride in halves (padded, conflict-free)
#define BST   72
#define A_HALVES (BM*AST)                 // 9216
#define B_HALVES (256*BST)                // 18432
#define STG_HALVES (A_HALVES + B_HALVES)  // 27648 (55296 B)
#define SMEM_BYTES (NBUF*STG_HALVES*2)    // 221184

__device__ __half d_WT[(size_t)4*2048*4096];   // 64 MB
__device__ __half d_XH[(size_t)4096*4096];     // 32 MB

__device__ __forceinline__ uint32_t su32(const void* p) {
    return (uint32_t)__cvta_generic_to_shared(p);
}
__device__ __forceinline__ void cp16(uint32_t d, const void* s) {
    asm volatile("cp.async.cg.shared.global [%0], [%1], 16;" :: "r"(d), "l"(s));
}
__device__ __forceinline__ void ldsm4(uint32_t* r, uint32_t a) {
    asm volatile("ldmatrix.sync.aligned.m8n8.x4.shared.b16 {%0,%1,%2,%3}, [%4];"
                 : "=r"(r[0]), "=r"(r[1]), "=r"(r[2]), "=r"(r[3]) : "r"(a));
}
__device__ __forceinline__ void mma16816(float* c, const uint32_t* a, const uint32_t* b) {
    asm volatile("mma.sync.aligned.m16n8k16.row.col.f32.f16.f16.f32 "
                 "{%0,%1,%2,%3}, {%4,%5,%6,%7}, {%8,%9}, {%0,%1,%2,%3};"
                 : "+f"(c[0]), "+f"(c[1]), "+f"(c[2]), "+f"(c[3])
                 : "r"(a[0]), "r"(a[1]), "r"(a[2]), "r"(a[3]), "r"(b[0]), "r"(b[1]));
}

// ---- pre-pass: transpose + convert weights: WT[g*2048+n][ph*2048+k] ----
__global__ void prep_w(const float* __restrict__ w0, const float* __restrict__ w1,
                       const float* __restrict__ w2, const float* __restrict__ w3,
                       const float* __restrict__ w4, const float* __restrict__ w5,
                       const float* __restrict__ w6, const float* __restrict__ w7) {
    __shared__ float t[32][33];
    const int z = blockIdx.z;                 // phase = z>>2, gate = z&3
    const float* W;
    switch (z) {
        case 0: W = w0; break; case 1: W = w1; break;
        case 2: W = w2; break; case 3: W = w3; break;
        case 4: W = w4; break; case 5: W = w5; break;
        case 6: W = w6; break; default: W = w7; break;
    }
    const int k0 = blockIdx.x * 32, n0 = blockIdx.y * 32;
    const int tx = threadIdx.x, ty = threadIdx.y;
    #pragma unroll
    for (int j = 0; j < 4; j++)
        t[ty + j * 8][tx] = W[(size_t)(k0 + ty + j * 8) * HD + n0 + tx];
    __syncthreads();
    const int gate = z & 3, phase = z >> 2;
    #pragma unroll
    for (int j = 0; j < 4; j++)
        d_WT[(size_t)(gate * 2048 + n0 + ty + j * 8) * KTOT + phase * 2048 + k0 + tx] =
            __float2half_rn(t[tx][ty + j * 8]);
}

// ---- pre-pass: pack + convert activations: XH[b] = [x | h] ----
__global__ void prep_a(const float* __restrict__ x, const float* __restrict__ h) {
    const int idx = blockIdx.x * 256 + threadIdx.x;    // one float4 -> 4 halves
    const int b = idx >> 10;
    const int k = (idx & 1023) * 4;
    const float* s = (k < HD) ? (x + (size_t)b * HD + k)
                              : (h + (size_t)b * HD + (k - HD));
    float4 v = *(const float4*)s;
    __half2 lo = __floats2half2_rn(v.x, v.y);
    __half2 hi = __floats2half2_rn(v.z, v.w);
    *(uint2*)(d_XH + (size_t)b * KTOT + k) =
        make_uint2(*(uint32_t*)&lo, *(uint32_t*)&hi);
}

// ---- main fused GEMM + LSTM epilogue ----
__global__ void __launch_bounds__(256, 1)
lstm_hmma(const float* __restrict__ cin,
          const float* __restrict__ bi, const float* __restrict__ bf,
          const float* __restrict__ bo, const float* __restrict__ bc,
          float* __restrict__ out) {
    extern __shared__ __half smem[];
    const int tid = threadIdx.x, lane = tid & 31, warp = tid >> 5;
    const int warpM = warp & 1;        // 2 warps along M (64 rows)
    const int warpN = warp >> 1;       // 4 warps along N (16 cols/gate)
    const int rowBase = blockIdx.x * BM;
    const int colBase = blockIdx.y * BN;

    float acc[4][4][2][4];
    #pragma unroll
    for (int g = 0; g < 4; g++)
        #pragma unroll
        for (int m = 0; m < 4; m++)
            #pragma unroll
            for (int n = 0; n < 2; n++)
                #pragma unroll
                for (int r = 0; r < 4; r++) acc[g][m][n][r] = 0.0f;

    // ldmatrix per-lane source offsets (halves), k16-invariant parts
    const int mi = lane >> 3;
    const int aRow = warpM * 64 + (lane & 7) + (mi & 1) * 8;     // + mtile*16
    const int aKoff = (mi >> 1) * 8;                              // + k16*16
    const int bRow = warpN * 16 + (lane & 7) + (mi >> 1) * 8;    // + g*64
    const int bKoff = (mi & 1) * 8;

    auto load_stage = [&](int s, int buf) {
        __half* st = smem + buf * STG_HALVES;
        const int kb = s * BK;
        // A: 128 rows x 64 halves = 1024 x 16B chunks
        #pragma unroll
        for (int i = 0; i < 4; i++) {
            const int ci = i * 256 + tid;
            const int r = ci >> 3, kc = ci & 7;
            cp16(su32(st + r * AST + kc * 8),
                 d_XH + (size_t)(rowBase + r) * KTOT + kb + kc * 8);
        }
        // B: 256 n-rows x 64 halves = 2048 x 16B chunks
        __half* sb = st + A_HALVES;
        #pragma unroll
        for (int i = 0; i < 8; i++) {
            const int ci = i * 256 + tid;
            const int n = ci >> 3, kc = ci & 7;
            const int g = n >> 6, nc = colBase + (n & 63);
            cp16(su32(sb + n * BST + kc * 8),
                 d_WT + (size_t)(g * 2048 + nc) * KTOT + kb + kc * 8);
        }
        asm volatile("cp.async.commit_group;");
    };

    // depth-3 preload
    load_stage(0, 0);
    load_stage(1, 1);
    load_stage(2, 2);

    for (int s = 0; s < NSTG; s++) {
        // stage s complete; up to 2 younger groups may remain in flight
        if (s <= NSTG - 3)      asm volatile("cp.async.wait_group 2;" ::: "memory");
        else if (s == NSTG - 2) asm volatile("cp.async.wait_group 1;" ::: "memory");
        else                    asm volatile("cp.async.wait_group 0;" ::: "memory");
        __syncthreads();   // single barrier per stage: also proves buffer (s-1)%4 drained

        if (s + 3 < NSTG) load_stage(s + 3, (s + 3) % NBUF);

        const __half* st = smem + (s % NBUF) * STG_HALVES;
        const uint32_t sA = su32(st);
        const uint32_t sB = su32(st + A_HALVES);

        #pragma unroll
        for (int k16 = 0; k16 < 4; k16++) {
            uint32_t a[4][4];
            #pragma unroll
            for (int m = 0; m < 4; m++)
                ldsm4(a[m], sA + ((aRow + m * 16) * AST + k16 * 16 + aKoff) * 2);
            #pragma unroll
            for (int g = 0; g < 4; g++) {
                uint32_t b[4];
                ldsm4(b, sB + ((g * 64 + bRow) * BST + k16 * 16 + bKoff) * 2);
                #pragma unroll
                for (int m = 0; m < 4; m++) {
                    mma16816(acc[g][m][0], a[m], b);
                    mma16816(acc[g][m][1], a[m], b + 2);
                }
            }
        }
    }

    // ---- fused epilogue: bias + activations + cell update ----
    const int r0 = rowBase + warpM * 64 + (lane >> 2);
    const int c0 = colBase + warpN * 16 + (lane & 3) * 2;
    const size_t BH = (size_t)BB * HD;

    #pragma unroll
    for (int m = 0; m < 4; m++) {
        #pragma unroll
        for (int n = 0; n < 2; n++) {
            #pragma unroll
            for (int rr = 0; rr < 2; rr++) {
                const int row = r0 + m * 16 + rr * 8;
                #pragma unroll
                for (int cc = 0; cc < 2; cc++) {
                    const int col = c0 + n * 8 + cc;
                    const int ai = rr * 2 + cc;
                    float gi = acc[0][m][n][ai] + bi[col];
                    float gf = acc[1][m][n][ai] + bf[col];
                    float go = acc[2][m][n][ai] + bo[col];
                    float gc = acc[3][m][n][ai] + bc[col];
                    float it = 1.f / (1.f + __expf(-gi));
                    float ft = 1.f / (1.f + __expf(-gf));
                    float ot = 1.f / (1.f + __expf(-go));
                    float gt = 1.f - 2.f / (__expf(2.f * gc) + 1.f);
                    float cv = cin[(size_t)row * HD + col];
                    float ct = cv * ft + it * gt;
                    float ht = ot * (1.f - 2.f / (__expf(2.f * ct) + 1.f));
                    out[(size_t)row * HD + col] = ht;
                    out[BH + (size_t)row * HD + col] = ct;
                }
            }
        }
    }
}

extern "C" void kernel_launch(void* const* d_in, const int* in_sizes, int n_in,
                              void* d_out, int out_size) {
    (void)in_sizes; (void)n_in; (void)out_size;
    const float* x   = (const float*)d_in[0];
    const float* h   = (const float*)d_in[1];
    const float* c   = (const float*)d_in[2];
    const float* wxi = (const float*)d_in[3];
    const float* wxf = (const float*)d_in[4];
    const float* wxo = (const float*)d_in[5];
    const float* wxc = (const float*)d_in[6];
    const float* whi = (const float*)d_in[7];
    const float* whf = (const float*)d_in[8];
    const float* who = (const float*)d_in[9];
    const float* whc = (const float*)d_in[10];
    const float* bi  = (const float*)d_in[11];
    const float* bf  = (const float*)d_in[12];
    const float* bo  = (const float*)d_in[13];
    const float* bc  = (const float*)d_in[14];
    float* out = (float*)d_out;

    cudaFuncSetAttribute(lstm_hmma,
                         cudaFuncAttributeMaxDynamicSharedMemorySize, SMEM_BYTES);

    prep_a<<<(BB * KTOT / 4) / 256, 256>>>(x, h);
    prep_w<<<dim3(64, 64, 8), dim3(32, 8)>>>(wxi, wxf, wxo, wxc, whi, whf, who, whc);
    lstm_hmma<<<dim3(BB / BM, HD / BN), 256, SMEM_BYTES>>>(c, bi, bf, bo, bc, out);
}

// round 9
// speedup vs baseline: 3.2323x; 1.1319x over previous
#include <cuda_runtime.h>
#include <cuda_fp16.h>
#include <cstdint>

// ---------------------------------------------------------------------------
// LSTM cell, fp16 mma.sync (m16n8k16) GEMM + fused epilogue.
//  Pre-pass 1: WT[gate*2048+n][k] = half(W[k][n]),  k = [x-phase | h-phase]
//  Pre-pass 2: XH[b][k] = half([x|h][b][k])
//  Main: CTA = 128 rows x (4 gates x 32 cols), fp32 acc in regs,
//        ldmatrix loads, BK=64, NBUF=3, 2 CTAs/SM for bubble hiding.
//  Out: [h_t ; c_t], fp32.
// ---------------------------------------------------------------------------

#define HD    2048
#define BB    4096
#define KTOT  4096
#define BM    128
#define BN    32            // cols per gate per CTA
#define BK    64            // halves per stage
#define NSTG  (KTOT/BK)     // 64
#define NBUF  3
#define AST   72            // smem stride in halves (padded, conflict-free)
#define BST   72
#define A_HALVES (BM*AST)                 // 9216
#define B_HALVES (128*BST)                // 9216  (4 gates x 32 cols)
#define STG_HALVES (A_HALVES + B_HALVES)  // 18432 (36864 B)
#define SMEM_BYTES (NBUF*STG_HALVES*2)    // 110592

__device__ __half d_WT[(size_t)4*2048*4096];   // 64 MB
__device__ __half d_XH[(size_t)4096*4096];     // 32 MB

__device__ __forceinline__ uint32_t su32(const void* p) {
    return (uint32_t)__cvta_generic_to_shared(p);
}
__device__ __forceinline__ void cp16(uint32_t d, const void* s) {
    asm volatile("cp.async.cg.shared.global [%0], [%1], 16;" :: "r"(d), "l"(s));
}
__device__ __forceinline__ void ldsm4(uint32_t* r, uint32_t a) {
    asm volatile("ldmatrix.sync.aligned.m8n8.x4.shared.b16 {%0,%1,%2,%3}, [%4];"
                 : "=r"(r[0]), "=r"(r[1]), "=r"(r[2]), "=r"(r[3]) : "r"(a));
}
__device__ __forceinline__ void ldsm2(uint32_t* r, uint32_t a) {
    asm volatile("ldmatrix.sync.aligned.m8n8.x2.shared.b16 {%0,%1}, [%2];"
                 : "=r"(r[0]), "=r"(r[1]) : "r"(a));
}
__device__ __forceinline__ void mma16816(float* c, const uint32_t* a, const uint32_t* b) {
    asm volatile("mma.sync.aligned.m16n8k16.row.col.f32.f16.f16.f32 "
                 "{%0,%1,%2,%3}, {%4,%5,%6,%7}, {%8,%9}, {%0,%1,%2,%3};"
                 : "+f"(c[0]), "+f"(c[1]), "+f"(c[2]), "+f"(c[3])
                 : "r"(a[0]), "r"(a[1]), "r"(a[2]), "r"(a[3]), "r"(b[0]), "r"(b[1]));
}

// ---- pre-pass: transpose + convert weights: WT[g*2048+n][ph*2048+k] ----
__global__ void prep_w(const float* __restrict__ w0, const float* __restrict__ w1,
                       const float* __restrict__ w2, const float* __restrict__ w3,
                       const float* __restrict__ w4, const float* __restrict__ w5,
                       const float* __restrict__ w6, const float* __restrict__ w7) {
    __shared__ float t[32][33];
    const int z = blockIdx.z;                 // phase = z>>2, gate = z&3
    const float* W;
    switch (z) {
        case 0: W = w0; break; case 1: W = w1; break;
        case 2: W = w2; break; case 3: W = w3; break;
        case 4: W = w4; break; case 5: W = w5; break;
        case 6: W = w6; break; default: W = w7; break;
    }
    const int k0 = blockIdx.x * 32, n0 = blockIdx.y * 32;
    const int tx = threadIdx.x, ty = threadIdx.y;
    #pragma unroll
    for (int j = 0; j < 4; j++)
        t[ty + j * 8][tx] = W[(size_t)(k0 + ty + j * 8) * HD + n0 + tx];
    __syncthreads();
    const int gate = z & 3, phase = z >> 2;
    #pragma unroll
    for (int j = 0; j < 4; j++)
        d_WT[(size_t)(gate * 2048 + n0 + ty + j * 8) * KTOT + phase * 2048 + k0 + tx] =
            __float2half_rn(t[tx][ty + j * 8]);
}

// ---- pre-pass: pack + convert activations: XH[b] = [x | h] ----
__global__ void prep_a(const float* __restrict__ x, const float* __restrict__ h) {
    const int idx = blockIdx.x * 256 + threadIdx.x;    // one float4 -> 4 halves
    const int b = idx >> 10;
    const int k = (idx & 1023) * 4;
    const float* s = (k < HD) ? (x + (size_t)b * HD + k)
                              : (h + (size_t)b * HD + (k - HD));
    float4 v = *(const float4*)s;
    __half2 lo = __floats2half2_rn(v.x, v.y);
    __half2 hi = __floats2half2_rn(v.z, v.w);
    *(uint2*)(d_XH + (size_t)b * KTOT + k) =
        make_uint2(*(uint32_t*)&lo, *(uint32_t*)&hi);
}

// ---- main fused GEMM + LSTM epilogue ----
__global__ void __launch_bounds__(256, 2)
lstm_hmma(const float* __restrict__ cin,
          const float* __restrict__ bi, const float* __restrict__ bf,
          const float* __restrict__ bo, const float* __restrict__ bc,
          float* __restrict__ out) {
    extern __shared__ __half smem[];
    const int tid = threadIdx.x, lane = tid & 31, warp = tid >> 5;
    const int warpM = warp & 1;        // 2 warps along M (64 rows each)
    const int warpN = warp >> 1;       // 4 warps along N (8 cols/gate each)
    const int rowBase = blockIdx.x * BM;
    const int colBase = blockIdx.y * BN;

    float acc[4][4][4];                // [gate][mtile][frag]
    #pragma unroll
    for (int g = 0; g < 4; g++)
        #pragma unroll
        for (int m = 0; m < 4; m++)
            #pragma unroll
            for (int r = 0; r < 4; r++) acc[g][m][r] = 0.0f;

    // ldmatrix per-lane source offsets (halves)
    const int mi = lane >> 3;                                    // 0..3
    const int aRow = warpM * 64 + (lane & 7) + (mi & 1) * 8;     // + mtile*16
    const int aKoff = (mi >> 1) * 8;                             // + k16*16
    const int l16 = lane & 15;                                   // x2 uses lanes 0-15
    const int bRow = warpN * 8 + (l16 & 7);                      // + g*32
    const int bKoff = (l16 >> 3) * 8;                            // + k16*16

    auto load_stage = [&](int s, int buf) {
        __half* st = smem + buf * STG_HALVES;
        const int kb = s * BK;
        // A: 128 rows x 64 halves = 1024 x 16B chunks
        #pragma unroll
        for (int i = 0; i < 4; i++) {
            const int ci = i * 256 + tid;
            const int r = ci >> 3, kc = ci & 7;
            cp16(su32(st + r * AST + kc * 8),
                 d_XH + (size_t)(rowBase + r) * KTOT + kb + kc * 8);
        }
        // B: 128 n-rows (4g x 32) x 64 halves = 1024 x 16B chunks
        __half* sb = st + A_HALVES;
        #pragma unroll
        for (int i = 0; i < 4; i++) {
            const int ci = i * 256 + tid;
            const int n = ci >> 3, kc = ci & 7;
            const int g = n >> 5, nc = colBase + (n & 31);
            cp16(su32(sb + n * BST + kc * 8),
                 d_WT + (size_t)(g * 2048 + nc) * KTOT + kb + kc * 8);
        }
        asm volatile("cp.async.commit_group;");
    };

    load_stage(0, 0);
    load_stage(1, 1);

    for (int s = 0; s < NSTG; s++) {
        if (s < NSTG - 1) asm volatile("cp.async.wait_group 1;" ::: "memory");
        else              asm volatile("cp.async.wait_group 0;" ::: "memory");
        __syncthreads();   // single barrier/stage; proves buffer (s-1)%3 drained

        if (s + 2 < NSTG) load_stage(s + 2, (s + 2) % NBUF);

        const __half* st = smem + (s % NBUF) * STG_HALVES;
        const uint32_t sA = su32(st);
        const uint32_t sB = su32(st + A_HALVES);

        #pragma unroll
        for (int k16 = 0; k16 < 4; k16++) {
            uint32_t a[4][4];
            #pragma unroll
            for (int m = 0; m < 4; m++)
                ldsm4(a[m], sA + ((aRow + m * 16) * AST + k16 * 16 + aKoff) * 2);
            #pragma unroll
            for (int g = 0; g < 4; g++) {
                uint32_t b[2];
                ldsm2(b, sB + ((g * 32 + bRow) * BST + k16 * 16 + bKoff) * 2);
                #pragma unroll
                for (int m = 0; m < 4; m++)
                    mma16816(acc[g][m], a[m], b);
            }
        }
    }

    // ---- fused epilogue: bias + activations + cell update ----
    const int r0 = rowBase + warpM * 64 + (lane >> 2);
    const int c0 = colBase + warpN * 8 + (lane & 3) * 2;
    const size_t BH = (size_t)BB * HD;

    #pragma unroll
    for (int m = 0; m < 4; m++) {
        #pragma unroll
        for (int rr = 0; rr < 2; rr++) {
            const int row = r0 + m * 16 + rr * 8;
            #pragma unroll
            for (int cc = 0; cc < 2; cc++) {
                const int col = c0 + cc;
                const int ai = rr * 2 + cc;
                float gi = acc[0][m][ai] + bi[col];
                float gf = acc[1][m][ai] + bf[col];
                float go = acc[2][m][ai] + bo[col];
                float gc = acc[3][m][ai] + bc[col];
                float it = 1.f / (1.f + __expf(-gi));
                float ft = 1.f / (1.f + __expf(-gf));
                float ot = 1.f / (1.f + __expf(-go));
                float gt = 1.f - 2.f / (__expf(2.f * gc) + 1.f);
                float cv = cin[(size_t)row * HD + col];
                float ct = cv * ft + it * gt;
                float ht = ot * (1.f - 2.f / (__expf(2.f * ct) + 1.f));
                out[(size_t)row * HD + col] = ht;
                out[BH + (size_t)row * HD + col] = ct;
            }
        }
    }
}

extern "C" void kernel_launch(void* const* d_in, const int* in_sizes, int n_in,
                              void* d_out, int out_size) {
    (void)in_sizes; (void)n_in; (void)out_size;
    const float* x   = (const float*)d_in[0];
    const float* h   = (const float*)d_in[1];
    const float* c   = (const float*)d_in[2];
    const float* wxi = (const float*)d_in[3];
    const float* wxf = (const float*)d_in[4];
    const float* wxo = (const float*)d_in[5];
    const float* wxc = (const float*)d_in[6];
    const float* whi = (const float*)d_in[7];
    const float* whf = (const float*)d_in[8];
    const float* who = (const float*)d_in[9];
    const float* whc = (const float*)d_in[10];
    const float* bi  = (const float*)d_in[11];
    const float* bf  = (const float*)d_in[12];
    const float* bo  = (const float*)d_in[13];
    const float* bc  = (const float*)d_in[14];
    float* out = (float*)d_out;

    cudaFuncSetAttribute(lstm_hmma,
                         cudaFuncAttributeMaxDynamicSharedMemorySize, SMEM_BYTES);

    prep_a<<<(BB * KTOT / 4) / 256, 256>>>(x, h);
    prep_w<<<dim3(64, 64, 8), dim3(32, 8)>>>(wxi, wxf, wxo, wxc, whi, whf, who, whc);
    lstm_hmma<<<dim3(BB / BM, HD / BN), 256, SMEM_BYTES>>>(c, bi, bf, bo, bc, out);
}